// round 2
// baseline (speedup 1.0000x reference)
#include <cuda_runtime.h>
#include <cuda_bf16.h>
#include <mma.h>

using namespace nvcuda;

#define EPSF 1e-6f

// Fixed problem maxima (I=16384, J=K=8192, D=128, E=2e6)
#define MAX_I 16384
#define MAX_M 16384   // J + K
#define DDIM  128

// ---- device scratch (static __device__ arrays; no allocation) ----
__device__ __nv_bfloat16 g_abf[(size_t)MAX_M * DDIM];   // rows: (r+eps) then (u+eps)
__device__ __nv_bfloat16 g_lbf[(size_t)MAX_I * DDIM];   // l
__device__ float g_na[MAX_M];     // |row|^2 of a
__device__ float g_bias[MAX_M];   // nu-eps / tau-eps per row
__device__ float g_nb[MAX_I];     // |l_i|^2
__device__ float g_colA[MAX_I];   // sum_j exp(nu_j - d_rl[j,i])
__device__ float g_colB[MAX_I];   // sum_k exp(tau_k - d_ul[k,i])
__device__ double g_z2;           // link-term accumulator

// ---------------------------------------------------------------
__global__ void init_kernel(int I) {
    int t = blockIdx.x * blockDim.x + threadIdx.x;
    if (t < I) { g_colA[t] = 0.f; g_colB[t] = 0.f; }
    if (t == 0) g_z2 = 0.0;
}

// One warp per row: fp32 -> (x+addEps) -> bf16, plus row norm + bias.
// isA=1 -> g_abf/g_na/g_bias at dstRowOffset; isA=0 -> g_lbf/g_nb.
__global__ void conv_kernel(const float* __restrict__ src,
                            const float* __restrict__ biasvec,
                            int rows, int dstRowOffset, int isA, float addEps) {
    int w    = blockIdx.x * (blockDim.x >> 5) + (threadIdx.x >> 5);
    int lane = threadIdx.x & 31;
    if (w >= rows) return;
    const float4 v4 = ((const float4*)(src + (size_t)w * DDIM))[lane];
    float x = v4.x + addEps, y = v4.y + addEps, z = v4.z + addEps, t = v4.w + addEps;
    float nrm = x * x + y * y + z * z + t * t;
    #pragma unroll
    for (int o = 16; o; o >>= 1) nrm += __shfl_xor_sync(0xFFFFFFFFu, nrm, o);
    int dr = dstRowOffset + w;
    __nv_bfloat16* dst = (isA ? g_abf : g_lbf) + (size_t)dr * DDIM + lane * 4;
    dst[0] = __float2bfloat16(x);
    dst[1] = __float2bfloat16(y);
    dst[2] = __float2bfloat16(z);
    dst[3] = __float2bfloat16(t);
    if (lane == 0) {
        if (isA) { g_na[dr] = nrm; g_bias[dr] = biasvec[w] - EPSF; }
        else       g_nb[dr] = nrm;
    }
}

// ---------------------------------------------------------------
// Distance GEMM + exp/column-reduce epilogue.
// Block tile 128x128, full K=128 in SMEM (bf16, pitch 144 for 32B-aligned rows).
// 8 warps in 4x2 layout, each 32x64 via 2x4 wmma 16x16x16 fragments.
#define APITCH 144
#define CPITCH 136
#define GEMM_SMEM (2 * 128 * APITCH * (int)sizeof(__nv_bfloat16))  // 73728 B

extern __shared__ char smem_raw[];

__global__ void dist_gemm_kernel(int M, int I, int J) {
    __nv_bfloat16* As = (__nv_bfloat16*)smem_raw;        // [128][144]
    __nv_bfloat16* Bs = As + 128 * APITCH;               // [128][144]
    float*         Cs = (float*)smem_raw;                // [128][136] (reused)

    int tid  = threadIdx.x;
    int row0 = blockIdx.y * 128;   // rows of the combined (r|u) matrix
    int col0 = blockIdx.x * 128;   // rows of l (== distance columns)

    // Load both 128x128 bf16 tiles (16 uint4 per row).
    {
        const uint4* ga = (const uint4*)(g_abf + (size_t)row0 * DDIM);
        const uint4* gb = (const uint4*)(g_lbf + (size_t)col0 * DDIM);
        #pragma unroll
        for (int idx = tid; idx < 2048; idx += 256) {
            int r = idx >> 4, c = idx & 15;
            *(uint4*)(As + r * APITCH + c * 8) = ga[r * 16 + c];
            *(uint4*)(Bs + r * APITCH + c * 8) = gb[r * 16 + c];
        }
    }
    __syncthreads();

    int warp = tid >> 5;
    int wm = warp & 3;   // 4 row-slabs of 32
    int wn = warp >> 2;  // 2 col-slabs of 64

    wmma::fragment<wmma::accumulator, 16, 16, 16, float> acc[2][4];
    #pragma unroll
    for (int i = 0; i < 2; i++)
        #pragma unroll
        for (int j = 0; j < 4; j++) wmma::fill_fragment(acc[i][j], 0.0f);

    #pragma unroll
    for (int kk = 0; kk < 8; kk++) {
        wmma::fragment<wmma::matrix_a, 16, 16, 16, __nv_bfloat16, wmma::row_major> af[2];
        wmma::fragment<wmma::matrix_b, 16, 16, 16, __nv_bfloat16, wmma::col_major> bf[4];
        #pragma unroll
        for (int i = 0; i < 2; i++)
            wmma::load_matrix_sync(af[i], As + (wm * 32 + i * 16) * APITCH + kk * 16, APITCH);
        #pragma unroll
        for (int j = 0; j < 4; j++)
            wmma::load_matrix_sync(bf[j], Bs + (wn * 64 + j * 16) * APITCH + kk * 16, APITCH);
        #pragma unroll
        for (int i = 0; i < 2; i++)
            #pragma unroll
            for (int j = 0; j < 4; j++)
                wmma::mma_sync(acc[i][j], af[i], bf[j], acc[i][j]);
    }
    __syncthreads();  // done reading As/Bs; reuse as Cs

    #pragma unroll
    for (int i = 0; i < 2; i++)
        #pragma unroll
        for (int j = 0; j < 4; j++)
            wmma::store_matrix_sync(Cs + (wm * 32 + i * 16) * CPITCH + (wn * 64 + j * 16),
                                    acc[i][j], CPITCH, wmma::mem_row_major);

    __shared__ float s_na[128], s_bias[128];
    if (tid < 128) { s_na[tid] = g_na[row0 + tid]; s_bias[tid] = g_bias[row0 + tid]; }
    __syncthreads();

    if (tid < 128) {
        float nb  = g_nb[col0 + tid];
        float sum = 0.f;
        #pragma unroll 4
        for (int m = 0; m < 128; m++) {
            float d2 = fmaxf(s_na[m] + nb - 2.0f * Cs[m * CPITCH + tid], 0.f);
            sum += __expf(s_bias[m] - sqrtf(d2));
        }
        float* target = (row0 < J) ? g_colA : g_colB;
        atomicAdd(&target[col0 + tid], sum);
    }
}

// ---------------------------------------------------------------
// Link term: 8 lanes per edge, fp32, double-accumulated per block.
__global__ void edge_kernel(const float* __restrict__ l, const float* __restrict__ r,
                            const float* __restrict__ u, const float* __restrict__ rho,
                            const float* __restrict__ nu, const float* __restrict__ tau,
                            const float* __restrict__ w,
                            const int* __restrict__ si, const int* __restrict__ sj,
                            const int* __restrict__ sk, int E) {
    int tid = threadIdx.x;
    int gid = blockIdx.x * blockDim.x + tid;
    int e   = gid >> 3;
    int p   = tid & 7;
    float s1 = 0.f, s2 = 0.f, val = 0.f;
    if (e < E) {
        int i = si[e], j = sj[e], k = sk[e];
        const float4* lp = (const float4*)(l + (size_t)i * DDIM);
        const float4* rp = (const float4*)(r + (size_t)j * DDIM);
        const float4* up = (const float4*)(u + (size_t)k * DDIM);
        #pragma unroll
        for (int q = 0; q < 4; q++) {
            float4 lv = lp[p + 8 * q];
            float4 rv = rp[p + 8 * q];
            float4 uv = up[p + 8 * q];
            float d;
            d = lv.x - rv.x + EPSF; s1 += d * d;
            d = lv.y - rv.y + EPSF; s1 += d * d;
            d = lv.z - rv.z + EPSF; s1 += d * d;
            d = lv.w - rv.w + EPSF; s1 += d * d;
            d = lv.x - uv.x + EPSF; s2 += d * d;
            d = lv.y - uv.y + EPSF; s2 += d * d;
            d = lv.z - uv.z + EPSF; s2 += d * d;
            d = lv.w - uv.w + EPSF; s2 += d * d;
        }
    }
    #pragma unroll
    for (int o = 4; o; o >>= 1) {
        s1 += __shfl_xor_sync(0xFFFFFFFFu, s1, o);
        s2 += __shfl_xor_sync(0xFFFFFFFFu, s2, o);
    }
    if (e < E && p == 0) {
        int i = si[e], j = sj[e], k = sk[e];
        val = w[e] * (rho[i] + nu[j] + tau[k] - sqrtf(s1) - sqrtf(s2));
    }
    // combine the 4 group leaders in each warp (other lanes carry 0)
    val += __shfl_xor_sync(0xFFFFFFFFu, val, 8);
    val += __shfl_xor_sync(0xFFFFFFFFu, val, 16);
    __shared__ float wsum[8];
    if ((tid & 31) == 0) wsum[tid >> 5] = val;
    __syncthreads();
    if (tid == 0) {
        float s = 0.f;
        #pragma unroll
        for (int q = 0; q < 8; q++) s += wsum[q];
        atomicAdd(&g_z2, (double)s);
    }
}

// ---------------------------------------------------------------
__global__ void final_kernel(const float* __restrict__ rho, float* __restrict__ out, int I) {
    __shared__ double sh[256];
    double s = 0.0;
    for (int i = threadIdx.x; i < I; i += blockDim.x)
        s += (double)(g_colA[i] * expf(rho[i]) * g_colB[i]);
    sh[threadIdx.x] = s;
    __syncthreads();
    for (int o = 128; o; o >>= 1) {
        if (threadIdx.x < o) sh[threadIdx.x] += sh[threadIdx.x + o];
        __syncthreads();
    }
    if (threadIdx.x == 0) out[0] = (float)(g_z2 - sh[0]);
}

// ---------------------------------------------------------------
extern "C" void kernel_launch(void* const* d_in, const int* in_sizes, int n_in,
                              void* d_out, int out_size) {
    const float* l   = (const float*)d_in[0];
    const float* r   = (const float*)d_in[1];
    const float* u   = (const float*)d_in[2];
    const float* rho = (const float*)d_in[3];
    const float* nu  = (const float*)d_in[4];
    const float* tau = (const float*)d_in[5];
    const float* sw  = (const float*)d_in[6];
    const int*   si  = (const int*)d_in[7];
    const int*   sj  = (const int*)d_in[8];
    const int*   sk  = (const int*)d_in[9];

    int I = in_sizes[3];
    int J = in_sizes[4];
    int K = in_sizes[5];
    int E = in_sizes[6];
    int M = J + K;

    init_kernel<<<(I + 255) / 256, 256>>>(I);

    conv_kernel<<<(J + 7) / 8, 256>>>(r, nu, J, 0, 1, EPSF);
    conv_kernel<<<(K + 7) / 8, 256>>>(u, tau, K, J, 1, EPSF);
    conv_kernel<<<(I + 7) / 8, 256>>>(l, nullptr, I, 0, 0, 0.f);

    cudaFuncSetAttribute(dist_gemm_kernel,
                         cudaFuncAttributeMaxDynamicSharedMemorySize, GEMM_SMEM);
    dim3 grid(I / 128, M / 128);
    dist_gemm_kernel<<<grid, 256, GEMM_SMEM>>>(M, I, J);

    edge_kernel<<<(E * 8 + 255) / 256, 256>>>(l, r, u, rho, nu, tau, sw, si, sj, sk, E);

    final_kernel<<<1, 256>>>(rho, (float*)d_out, I);
}

// round 5
// speedup vs baseline: 2.1614x; 2.1614x over previous
#include <cuda_runtime.h>
#include <cuda_bf16.h>
#include <mma.h>
#include <cstdint>

using namespace nvcuda;

#define EPSF 1e-6f
#define MAX_I 16384
#define MAX_M 16384
#define DDIM  128

// ---------------- device scratch ----------------
__device__ __align__(16) __nv_bfloat16 g_abf[(size_t)MAX_M * DDIM]; // (r+eps | u+eps)
__device__ __align__(16) __nv_bfloat16 g_lbf[(size_t)MAX_I * DDIM]; // l
__device__ __align__(16) float2 g_pna[MAX_M];  // {|row|^2, exp(bias-eps)}
__device__ float  g_nb[MAX_I];
__device__ float  g_colA[MAX_I];
__device__ float  g_colB[MAX_I];
__device__ double g_z2;

// ---------------- small kernels ----------------
__global__ void init_kernel(int I) {
    int t = blockIdx.x * blockDim.x + threadIdx.x;
    if (t < I) { g_colA[t] = 0.f; g_colB[t] = 0.f; }
    if (t == 0) g_z2 = 0.0;
}

__global__ void conv_kernel(const float* __restrict__ src, const float* __restrict__ biasvec,
                            int rows, int dstRowOffset, int isA, float addEps) {
    int w = blockIdx.x * (blockDim.x >> 5) + (threadIdx.x >> 5);
    int lane = threadIdx.x & 31;
    if (w >= rows) return;
    const float4 v4 = ((const float4*)(src + (size_t)w * DDIM))[lane];
    float x = v4.x + addEps, y = v4.y + addEps, z = v4.z + addEps, t = v4.w + addEps;
    float nrm = x * x + y * y + z * z + t * t;
    #pragma unroll
    for (int o = 16; o; o >>= 1) nrm += __shfl_xor_sync(0xFFFFFFFFu, nrm, o);
    int dr = dstRowOffset + w;
    __nv_bfloat16* dst = (isA ? g_abf : g_lbf) + (size_t)dr * DDIM + lane * 4;
    dst[0] = __float2bfloat16(x);
    dst[1] = __float2bfloat16(y);
    dst[2] = __float2bfloat16(z);
    dst[3] = __float2bfloat16(t);
    if (lane == 0) {
        if (isA) g_pna[dr] = make_float2(nrm, __expf(biasvec[w] - EPSF));
        else     g_nb[dr]  = nrm;
    }
}

// ---------------- fused GEMM + edge kernel ----------------
#define APITCH 144
#define CPITCH 136
#define GEMM_SMEM (2 * 128 * APITCH * (int)sizeof(__nv_bfloat16))  // 73728 B
#define NEDGE_BLK 2048

extern __shared__ char smem_raw[];

// bf16 pair (packed in a u32) minus bf16 pair, accumulate squared into s
__device__ __forceinline__ void acc_sq(uint32_t lw, uint32_t rw, float& s) {
    float lx = __uint_as_float(lw << 16);
    float hx = __uint_as_float(lw & 0xFFFF0000u);
    float ly = __uint_as_float(rw << 16);
    float hy = __uint_as_float(rw & 0xFFFF0000u);
    float d0 = lx - ly, d1 = hx - hy;
    s = fmaf(d0, d0, s);
    s = fmaf(d1, d1, s);
}

__global__ void __launch_bounds__(256, 2) fused_kernel(
    const float* __restrict__ rho, const float* __restrict__ nu, const float* __restrict__ tau,
    const float* __restrict__ sw,
    const int* __restrict__ si, const int* __restrict__ sj, const int* __restrict__ sk,
    int J, int E)
{
    int bid = blockIdx.x;
    int tid = threadIdx.x;

    __shared__ float2 s_pn[128];
    __shared__ float  wsum[8];

    if (bid % 9 == 0) {
        // ---------- edge path (bf16 tables; ~2x less L2 traffic) ----------
        int eb   = bid / 9;          // 0..2047
        int p    = tid & 7;
        int esub = tid >> 3;
        float lead = 0.f;
        for (int e = eb * 32 + esub; e < E; e += NEDGE_BLK * 32) {
            int i = si[e], j = sj[e], k = sk[e];
            const uint4* lp = (const uint4*)(g_lbf + (size_t)i * DDIM);
            const uint4* rp = (const uint4*)(g_abf + (size_t)j * DDIM);
            const uint4* up = (const uint4*)(g_abf + (size_t)(J + k) * DDIM);
            float s1 = 0.f, s2 = 0.f;
            #pragma unroll
            for (int q = 0; q < 2; q++) {
                uint4 lv = lp[p * 2 + q];
                uint4 rv = rp[p * 2 + q];
                uint4 uv = up[p * 2 + q];
                acc_sq(lv.x, rv.x, s1); acc_sq(lv.y, rv.y, s1);
                acc_sq(lv.z, rv.z, s1); acc_sq(lv.w, rv.w, s1);
                acc_sq(lv.x, uv.x, s2); acc_sq(lv.y, uv.y, s2);
                acc_sq(lv.z, uv.z, s2); acc_sq(lv.w, uv.w, s2);
            }
            #pragma unroll
            for (int o = 4; o; o >>= 1) {
                s1 += __shfl_xor_sync(0xFFFFFFFFu, s1, o);
                s2 += __shfl_xor_sync(0xFFFFFFFFu, s2, o);
            }
            if (p == 0)
                lead += sw[e] * (rho[i] + nu[j] + tau[k] - sqrtf(s1) - sqrtf(s2));
        }
        lead += __shfl_xor_sync(0xFFFFFFFFu, lead, 8);
        lead += __shfl_xor_sync(0xFFFFFFFFu, lead, 16);
        if ((tid & 31) == 0) wsum[tid >> 5] = lead;
        __syncthreads();
        if (tid == 0) {
            float s = 0.f;
            #pragma unroll
            for (int q = 0; q < 8; q++) s += wsum[q];
            atomicAdd(&g_z2, (double)s);
        }
        return;
    }

    // ---------- GEMM tile path ----------
    int gid   = bid - bid / 9 - 1;   // 0..16383
    int itile = gid & 127;
    int mtile = gid >> 7;
    int row0  = mtile * 128;         // combined-matrix rows
    int col0  = itile * 128;         // l rows (distance columns)

    __nv_bfloat16* As = (__nv_bfloat16*)smem_raw;
    __nv_bfloat16* Bs = As + 128 * APITCH;
    float*         Cs = (float*)smem_raw;   // reused after MMA

    {
        const uint4* ga = (const uint4*)(g_abf + (size_t)row0 * DDIM);
        const uint4* gb = (const uint4*)(g_lbf + (size_t)col0 * DDIM);
        #pragma unroll
        for (int t = 0; t < 8; t++) {
            int idx = tid + t * 256;
            int r = idx >> 4, c = idx & 15;
            *(uint4*)(As + r * APITCH + c * 8) = ga[idx];
            *(uint4*)(Bs + r * APITCH + c * 8) = gb[idx];
        }
    }
    if (tid < 128) s_pn[tid] = g_pna[row0 + tid];
    __syncthreads();

    int warp = tid >> 5;
    int wm = warp & 3;   // 4 row-slabs of 32
    int wn = warp >> 2;  // 2 col-slabs of 64

    wmma::fragment<wmma::accumulator, 16, 16, 16, float> acc[2][4];
    #pragma unroll
    for (int i = 0; i < 2; i++)
        #pragma unroll
        for (int j = 0; j < 4; j++) wmma::fill_fragment(acc[i][j], 0.0f);

    #pragma unroll
    for (int kk = 0; kk < 8; kk++) {
        wmma::fragment<wmma::matrix_a, 16, 16, 16, __nv_bfloat16, wmma::row_major> af[2];
        wmma::fragment<wmma::matrix_b, 16, 16, 16, __nv_bfloat16, wmma::col_major> bf[4];
        #pragma unroll
        for (int i = 0; i < 2; i++)
            wmma::load_matrix_sync(af[i], As + (wm * 32 + i * 16) * APITCH + kk * 16, APITCH);
        #pragma unroll
        for (int j = 0; j < 4; j++)
            wmma::load_matrix_sync(bf[j], Bs + (wn * 64 + j * 16) * APITCH + kk * 16, APITCH);
        #pragma unroll
        for (int i = 0; i < 2; i++)
            #pragma unroll
            for (int j = 0; j < 4; j++)
                wmma::mma_sync(acc[i][j], af[i], bf[j], acc[i][j]);
    }
    __syncthreads();  // done with As/Bs; reuse as Cs

    #pragma unroll
    for (int i = 0; i < 2; i++)
        #pragma unroll
        for (int j = 0; j < 4; j++)
            wmma::store_matrix_sync(Cs + (wm * 32 + i * 16) * CPITCH + (wn * 64 + j * 16),
                                    acc[i][j], CPITCH, wmma::mem_row_major);
    __syncthreads();

    // Epilogue: 256 threads, 2 per column, 64 rows each. Approx MUFU math.
    {
        int col  = tid & 127;
        int half = tid >> 7;
        float nb = g_nb[col0 + col];
        float val = 0.f;
        int m0 = half * 64;
        #pragma unroll 8
        for (int m = m0; m < m0 + 64; m++) {
            float2 pn = s_pn[m];
            float d2 = fmaxf(pn.x + nb - 2.0f * Cs[m * CPITCH + col], 0.f);
            float d, ex;
            asm("sqrt.approx.f32 %0, %1;" : "=f"(d) : "f"(d2));
            asm("ex2.approx.f32 %0, %1;" : "=f"(ex) : "f"(-1.4426950408889634f * d));
            val = fmaf(pn.y, ex, val);
        }
        float* target = (row0 < J) ? g_colA : g_colB;
        atomicAdd(&target[col0 + col], val);
    }
}

// ---------------- final reduce ----------------
__global__ void final_kernel(const float* __restrict__ rho, float* __restrict__ out, int I) {
    __shared__ double sh[256];
    double s = 0.0;
    for (int i = threadIdx.x; i < I; i += blockDim.x)
        s += (double)(g_colA[i] * expf(rho[i]) * g_colB[i]);
    sh[threadIdx.x] = s;
    __syncthreads();
    for (int o = 128; o; o >>= 1) {
        if (threadIdx.x < o) sh[threadIdx.x] += sh[threadIdx.x + o];
        __syncthreads();
    }
    if (threadIdx.x == 0) out[0] = (float)(g_z2 - sh[0]);
}

// ---------------- launcher ----------------
extern "C" void kernel_launch(void* const* d_in, const int* in_sizes, int n_in,
                              void* d_out, int out_size) {
    const float* l   = (const float*)d_in[0];
    const float* r   = (const float*)d_in[1];
    const float* u   = (const float*)d_in[2];
    const float* rho = (const float*)d_in[3];
    const float* nu  = (const float*)d_in[4];
    const float* tau = (const float*)d_in[5];
    const float* sw  = (const float*)d_in[6];
    const int*   si  = (const int*)d_in[7];
    const int*   sj  = (const int*)d_in[8];
    const int*   sk  = (const int*)d_in[9];

    int I = in_sizes[3];
    int J = in_sizes[4];
    int K = in_sizes[5];
    int E = in_sizes[6];
    int M = J + K;

    init_kernel<<<(I + 255) / 256, 256>>>(I);
    conv_kernel<<<(J + 7) / 8, 256>>>(r, nu, J, 0, 1, EPSF);
    conv_kernel<<<(K + 7) / 8, 256>>>(u, tau, K, J, 1, EPSF);
    conv_kernel<<<(I + 7) / 8, 256>>>(l, nullptr, I, 0, 0, 0.f);

    cudaFuncSetAttribute(fused_kernel, cudaFuncAttributeMaxDynamicSharedMemorySize, GEMM_SMEM);
    int ngemm = (M / 128) * (I / 128);   // 16384
    int grid  = ngemm + ngemm / 8;       // 18432: every 9th block = edge
    fused_kernel<<<grid, 256, GEMM_SMEM>>>(rho, nu, tau, sw, si, sj, sk, J, E);

    final_kernel<<<1, 256>>>(rho, (float*)d_out, I);
}

// round 6
// speedup vs baseline: 2.7769x; 1.2847x over previous
#include <cuda_runtime.h>
#include <cuda_bf16.h>
#include <cstdint>

#define EPSF 1e-6f
#define MAX_I 16384
#define MAX_M 16384
#define DDIM  128

// scaled-distance constants: d2' = 2.08137*d2 so exp(-d)=ex2(-sqrt(d2'))
#define SC   2.08136898f
#define SCM2 -4.16273796f

// ---------------- device scratch ----------------
__device__ __align__(16) __nv_bfloat16 g_abf[(size_t)MAX_M * DDIM]; // (r+eps | u+eps)
__device__ __align__(16) __nv_bfloat16 g_lbf[(size_t)MAX_I * DDIM]; // l
__device__ __align__(16) float2 g_pna[MAX_M];  // {SC*|row|^2, exp(bias-eps)}
__device__ float  g_nb[MAX_I];                 // SC*|l_i|^2
__device__ float  g_colA[MAX_I];
__device__ float  g_colB[MAX_I];
__device__ double g_z2;

__device__ __forceinline__ uint32_t smem_u32(const void* p) {
    uint32_t a;
    asm("{ .reg .u64 t; cvta.to.shared.u64 t, %1; cvt.u32.u64 %0, t; }" : "=r"(a) : "l"(p));
    return a;
}
#define CP_ASYNC16(dst, src) \
    asm volatile("cp.async.cg.shared.global [%0], [%1], 16;" :: "r"(dst), "l"(src))
#define CP_COMMIT() asm volatile("cp.async.commit_group;")
#define CP_WAIT(N)  asm volatile("cp.async.wait_group %0;" :: "n"(N))

__device__ __forceinline__ void ldm_x4(uint32_t& r0, uint32_t& r1, uint32_t& r2, uint32_t& r3,
                                       uint32_t addr) {
    asm volatile("ldmatrix.sync.aligned.m8n8.x4.shared.b16 {%0,%1,%2,%3}, [%4];"
                 : "=r"(r0), "=r"(r1), "=r"(r2), "=r"(r3) : "r"(addr));
}
__device__ __forceinline__ void mma_bf16(float* c, const uint32_t* a, uint32_t b0, uint32_t b1) {
    asm volatile("mma.sync.aligned.m16n8k16.row.col.f32.bf16.bf16.f32 "
                 "{%0,%1,%2,%3}, {%4,%5,%6,%7}, {%8,%9}, {%0,%1,%2,%3};"
                 : "+f"(c[0]), "+f"(c[1]), "+f"(c[2]), "+f"(c[3])
                 : "r"(a[0]), "r"(a[1]), "r"(a[2]), "r"(a[3]), "r"(b0), "r"(b1));
}
// exp(-sqrt(max(pnb + SCM2*v, 0))) * pny   (pnb pre-scaled by SC)
__device__ __forceinline__ float expterm(float v, float pnb, float pny) {
    float d2 = fmaf(v, SCM2, pnb);
    d2 = fmaxf(d2, 0.f);
    float d, ex;
    asm("sqrt.approx.f32 %0, %1;" : "=f"(d) : "f"(d2));
    asm("ex2.approx.f32 %0, %1;" : "=f"(ex) : "f"(-d));
    return pny * ex;
}

// ---------------- small kernels ----------------
__global__ void init_kernel(int I) {
    int t = blockIdx.x * blockDim.x + threadIdx.x;
    if (t < I) { g_colA[t] = 0.f; g_colB[t] = 0.f; }
    if (t == 0) g_z2 = 0.0;
}

__global__ void conv_kernel(const float* __restrict__ src, const float* __restrict__ biasvec,
                            int rows, int dstRowOffset, int isA, float addEps) {
    int w = blockIdx.x * (blockDim.x >> 5) + (threadIdx.x >> 5);
    int lane = threadIdx.x & 31;
    if (w >= rows) return;
    const float4 v4 = ((const float4*)(src + (size_t)w * DDIM))[lane];
    float x = v4.x + addEps, y = v4.y + addEps, z = v4.z + addEps, t = v4.w + addEps;
    float nrm = x * x + y * y + z * z + t * t;
    #pragma unroll
    for (int o = 16; o; o >>= 1) nrm += __shfl_xor_sync(0xFFFFFFFFu, nrm, o);
    int dr = dstRowOffset + w;
    __nv_bfloat16* dst = (isA ? g_abf : g_lbf) + (size_t)dr * DDIM + lane * 4;
    dst[0] = __float2bfloat16(x);
    dst[1] = __float2bfloat16(y);
    dst[2] = __float2bfloat16(z);
    dst[3] = __float2bfloat16(t);
    if (lane == 0) {
        if (isA) g_pna[dr] = make_float2(SC * nrm, __expf(biasvec[w] - EPSF));
        else     g_nb[dr]  = SC * nrm;
    }
}

// ---------------- fused GEMM + edge kernel ----------------
// SMEM: A double buffer (2 x 128 rows x 272B) + B (128 x 272B)
#define ROWB   272
#define AT_BYTES (128 * ROWB)            // 34816
#define SM_BYTES (3 * AT_BYTES)          // 104448
#define NEDGE_BLK 2048

extern __shared__ char smem_raw[];

__device__ __forceinline__ void acc_sq(uint32_t lw, uint32_t rw, float& s) {
    float lx = __uint_as_float(lw << 16);
    float hx = __uint_as_float(lw & 0xFFFF0000u);
    float ly = __uint_as_float(rw << 16);
    float hy = __uint_as_float(rw & 0xFFFF0000u);
    float d0 = lx - ly, d1 = hx - hy;
    s = fmaf(d0, d0, s);
    s = fmaf(d1, d1, s);
}

__global__ void __launch_bounds__(256, 2) fused_kernel(
    const float* __restrict__ rho, const float* __restrict__ nu, const float* __restrict__ tau,
    const float* __restrict__ sw,
    const int* __restrict__ si, const int* __restrict__ sj, const int* __restrict__ sk,
    int J, int E)
{
    int bid = blockIdx.x;
    int tid = threadIdx.x;

    if (bid % 5 == 0) {
        // ---------- edge path (bf16 tables) ----------
        __shared__ float wsum[8];
        int eb   = bid / 5;
        int p    = tid & 7;
        int esub = tid >> 3;
        float lead = 0.f;
        for (int e = eb * 32 + esub; e < E; e += NEDGE_BLK * 32) {
            int i = si[e], j = sj[e], k = sk[e];
            const uint4* lp = (const uint4*)(g_lbf + (size_t)i * DDIM);
            const uint4* rp = (const uint4*)(g_abf + (size_t)j * DDIM);
            const uint4* up = (const uint4*)(g_abf + (size_t)(J + k) * DDIM);
            float s1 = 0.f, s2 = 0.f;
            #pragma unroll
            for (int q = 0; q < 2; q++) {
                uint4 lv = lp[p * 2 + q];
                uint4 rv = rp[p * 2 + q];
                uint4 uv = up[p * 2 + q];
                acc_sq(lv.x, rv.x, s1); acc_sq(lv.y, rv.y, s1);
                acc_sq(lv.z, rv.z, s1); acc_sq(lv.w, rv.w, s1);
                acc_sq(lv.x, uv.x, s2); acc_sq(lv.y, uv.y, s2);
                acc_sq(lv.z, uv.z, s2); acc_sq(lv.w, uv.w, s2);
            }
            #pragma unroll
            for (int o = 4; o; o >>= 1) {
                s1 += __shfl_xor_sync(0xFFFFFFFFu, s1, o);
                s2 += __shfl_xor_sync(0xFFFFFFFFu, s2, o);
            }
            if (p == 0)
                lead += sw[e] * (rho[i] + nu[j] + tau[k] - sqrtf(s1) - sqrtf(s2));
        }
        lead += __shfl_xor_sync(0xFFFFFFFFu, lead, 8);
        lead += __shfl_xor_sync(0xFFFFFFFFu, lead, 16);
        if ((tid & 31) == 0) wsum[tid >> 5] = lead;
        __syncthreads();
        if (tid == 0) {
            float s = 0.f;
            #pragma unroll
            for (int q = 0; q < 8; q++) s += wsum[q];
            atomicAdd(&g_z2, (double)s);
        }
        return;
    }

    // ---------- GEMM path: 256(m) x 128(i) per block, 2 m-tiles ----------
    int gid   = bid - bid / 5 - 1;       // 0..8191
    int itile = gid & 127;
    int mtile = gid >> 7;                // 0..63
    int col0  = itile * 128;

    uint32_t sb = smem_u32(smem_raw);
    uint32_t A0b = sb, A1b = sb + AT_BYTES, Bb = sb + 2 * AT_BYTES;

    // issue all copies up front: group0 = B + A-tile0, group1 = A-tile1
    {
        int row = tid >> 4, c = tid & 15;
        const char* gB  = (const char*)(g_lbf + (size_t)col0 * DDIM);
        const char* gA0 = (const char*)(g_abf + (size_t)(mtile * 256) * DDIM);
        const char* gA1 = gA0 + 128 * 256;
        #pragma unroll
        for (int rr = 0; rr < 8; rr++) {
            uint32_t doff = (uint32_t)(row + rr * 16) * ROWB + c * 16;
            size_t   goff = (size_t)(row + rr * 16) * 256 + c * 16;
            CP_ASYNC16(Bb + doff, gB + goff);
            CP_ASYNC16(A0b + doff, gA0 + goff);
        }
        CP_COMMIT();
        #pragma unroll
        for (int rr = 0; rr < 8; rr++) {
            uint32_t doff = (uint32_t)(row + rr * 16) * ROWB + c * 16;
            size_t   goff = (size_t)(row + rr * 16) * 256 + c * 16;
            CP_ASYNC16(A1b + doff, gA1 + goff);
        }
        CP_COMMIT();
    }

    int lane = tid & 31, warp = tid >> 5;
    int wm = warp & 3, wn = warp >> 2;   // 4 m-slabs of 32, 2 i-slabs of 64
    int g = lane >> 2, tig = lane & 3;

    // per-thread column norms (pre-scaled), fixed for both tiles
    float nbc[8][2];
    #pragma unroll
    for (int nj = 0; nj < 8; nj++) {
        int i0 = col0 + wn * 64 + nj * 8 + 2 * tig;
        nbc[nj][0] = __ldg(&g_nb[i0]);
        nbc[nj][1] = __ldg(&g_nb[i0 + 1]);
    }

    CP_WAIT(1);
    __syncthreads();

    #pragma unroll
    for (int t = 0; t < 2; t++) {
        if (t == 1) { CP_WAIT(0); __syncthreads(); }
        int row0 = mtile * 256 + t * 128;
        uint32_t Ab = t ? A1b : A0b;

        // row norms + exp(bias) for this thread's 4 m positions
        float pnx[2][2], pny[2][2];
        #pragma unroll
        for (int mi = 0; mi < 2; mi++)
            #pragma unroll
            for (int h = 0; h < 2; h++) {
                float2 p = __ldg(&g_pna[row0 + wm * 32 + mi * 16 + g + h * 8]);
                pnx[mi][h] = p.x; pny[mi][h] = p.y;
            }

        float acc[2][8][4];
        #pragma unroll
        for (int mi = 0; mi < 2; mi++)
            #pragma unroll
            for (int nj = 0; nj < 8; nj++)
                #pragma unroll
                for (int q = 0; q < 4; q++) acc[mi][nj][q] = 0.f;

        uint32_t arowoff = (uint32_t)(wm * 32 + (lane & 15)) * ROWB;
        uint32_t browbase = (uint32_t)(wn * 64 + (lane & 7) + ((lane >> 4) << 3)) * ROWB;

        #pragma unroll
        for (int kk = 0; kk < 8; kk++) {
            uint32_t ka = (uint32_t)(kk * 32) + ((lane >> 4) << 4);
            uint32_t kb = (uint32_t)(kk * 32) + (((lane >> 3) & 1) << 4);
            uint32_t ar[2][4];
            ldm_x4(ar[0][0], ar[0][1], ar[0][2], ar[0][3], Ab + arowoff + ka);
            ldm_x4(ar[1][0], ar[1][1], ar[1][2], ar[1][3], Ab + arowoff + 16 * ROWB + ka);
            #pragma unroll
            for (int njp = 0; njp < 4; njp++) {
                uint32_t b0, b1, b2, b3;
                ldm_x4(b0, b1, b2, b3, Bb + browbase + (uint32_t)(njp * 16) * ROWB + kb);
                #pragma unroll
                for (int mi = 0; mi < 2; mi++) {
                    mma_bf16(acc[mi][2 * njp],     ar[mi], b0, b1);
                    mma_bf16(acc[mi][2 * njp + 1], ar[mi], b2, b3);
                }
            }
        }

        // fragment-direct epilogue: c0:(g,2tig) c1:(g,2tig+1) c2:(g+8,2tig) c3:(g+8,2tig+1)
        float slo[8], shi[8];
        #pragma unroll
        for (int nj = 0; nj < 8; nj++) { slo[nj] = 0.f; shi[nj] = 0.f; }
        #pragma unroll
        for (int mi = 0; mi < 2; mi++)
            #pragma unroll
            for (int nj = 0; nj < 8; nj++) {
                slo[nj] += expterm(acc[mi][nj][0], pnx[mi][0] + nbc[nj][0], pny[mi][0]);
                shi[nj] += expterm(acc[mi][nj][1], pnx[mi][0] + nbc[nj][1], pny[mi][0]);
                slo[nj] += expterm(acc[mi][nj][2], pnx[mi][1] + nbc[nj][0], pny[mi][1]);
                shi[nj] += expterm(acc[mi][nj][3], pnx[mi][1] + nbc[nj][1], pny[mi][1]);
            }

        float* target = (row0 < J) ? g_colA : g_colB;
        #pragma unroll
        for (int nj = 0; nj < 8; nj++) {
            #pragma unroll
            for (int o = 4; o < 32; o <<= 1) {
                slo[nj] += __shfl_xor_sync(0xFFFFFFFFu, slo[nj], o);
                shi[nj] += __shfl_xor_sync(0xFFFFFFFFu, shi[nj], o);
            }
            if (g == 0) {
                int i0 = col0 + wn * 64 + nj * 8 + 2 * tig;
                atomicAdd(&target[i0],     slo[nj]);
                atomicAdd(&target[i0 + 1], shi[nj]);
            }
        }
    }
}

// ---------------- final reduce ----------------
__global__ void final_kernel(const float* __restrict__ rho, float* __restrict__ out, int I) {
    __shared__ double sh[256];
    double s = 0.0;
    for (int i = threadIdx.x; i < I; i += blockDim.x)
        s += (double)(g_colA[i] * expf(rho[i]) * g_colB[i]);
    sh[threadIdx.x] = s;
    __syncthreads();
    for (int o = 128; o; o >>= 1) {
        if (threadIdx.x < o) sh[threadIdx.x] += sh[threadIdx.x + o];
        __syncthreads();
    }
    if (threadIdx.x == 0) out[0] = (float)(g_z2 - sh[0]);
}

// ---------------- launcher ----------------
extern "C" void kernel_launch(void* const* d_in, const int* in_sizes, int n_in,
                              void* d_out, int out_size) {
    const float* l   = (const float*)d_in[0];
    const float* r   = (const float*)d_in[1];
    const float* u   = (const float*)d_in[2];
    const float* rho = (const float*)d_in[3];
    const float* nu  = (const float*)d_in[4];
    const float* tau = (const float*)d_in[5];
    const float* sw  = (const float*)d_in[6];
    const int*   si  = (const int*)d_in[7];
    const int*   sj  = (const int*)d_in[8];
    const int*   sk  = (const int*)d_in[9];

    int I = in_sizes[3];
    int J = in_sizes[4];
    int K = in_sizes[5];
    int E = in_sizes[6];
    int M = J + K;

    init_kernel<<<(I + 255) / 256, 256>>>(I);
    conv_kernel<<<(J + 7) / 8, 256>>>(r, nu, J, 0, 1, EPSF);
    conv_kernel<<<(K + 7) / 8, 256>>>(u, tau, K, J, 1, EPSF);
    conv_kernel<<<(I + 7) / 8, 256>>>(l, nullptr, I, 0, 0, 0.f);

    cudaFuncSetAttribute(fused_kernel, cudaFuncAttributeMaxDynamicSharedMemorySize, SM_BYTES);
    int ngemm = (M / 256) * (I / 128);   // 8192
    int grid  = ngemm + ngemm / 4;       // 10240: every 5th block = edge
    fused_kernel<<<grid, 256, SM_BYTES>>>(rho, nu, tau, sw, si, sj, sk, J, E);

    final_kernel<<<1, 256>>>(rho, (float*)d_out, I);
}